// round 1
// baseline (speedup 1.0000x reference)
#include <cuda_runtime.h>
#include <math.h>
#include <stdint.h>

#define BB 32
#define GG 32
#define NN 8400
#define CC 80
#define TKK 10
#define EPSF 1e-9f

// ---------------- scratch (device globals; no allocs allowed) ----------------
__device__ float g_boxes[BB * NN * 4];                    // 4.3 MB
__device__ float g_align[(size_t)BB * GG * NN];           // 34.4 MB
__device__ float g_iou[(size_t)BB * GG * NN];             // 34.4 MB
__device__ int g_topk[BB * GG * TKK];
__device__ unsigned char g_fg[BB * NN];
__device__ int g_matched[BB * NN];
__device__ float g_alignat[BB * NN];
__device__ unsigned int g_posA[BB * GG];                  // float bits, atomicMax (nonneg)
__device__ unsigned int g_posI[BB * GG];
__device__ int g_fgcnt;
__device__ double g_bce;
__device__ double g_iou_sum;
__device__ double g_cross_sum;
__device__ double g_dfl_sum;

// ---------------- helpers ----------------
__device__ __forceinline__ void locate(int n, int& lvl, int& HW, int& local,
                                       float& cx, float& cy) {
    if (n < 6400) {
        lvl = 0; HW = 6400; local = n;
        int y = n / 80; int x = n - y * 80;
        cx = (x + 0.5f) * 8.0f; cy = (y + 0.5f) * 8.0f;
    } else if (n < 8000) {
        lvl = 1; HW = 1600; local = n - 6400;
        int y = local / 40; int x = local - y * 40;
        cx = (x + 0.5f) * 16.0f; cy = (y + 0.5f) * 16.0f;
    } else {
        lvl = 2; HW = 400; local = n - 8000;
        int y = local / 20; int x = local - y * 20;
        cx = (x + 0.5f) * 32.0f; cy = (y + 0.5f) * 32.0f;
    }
}

// ---------------- k_init: zero per-call accumulators ----------------
__global__ void k_init() {
    int i = blockIdx.x * blockDim.x + threadIdx.x;
    if (i < BB * GG) { g_posA[i] = 0u; g_posI[i] = 0u; }
    if (i == 0) {
        g_fgcnt = 0;
        g_bce = 0.0; g_iou_sum = 0.0; g_cross_sum = 0.0; g_dfl_sum = 0.0;
    }
}

// ---------------- k_decode: DFL -> pred boxes ----------------
__global__ void k_decode(const float* __restrict__ p0,
                         const float* __restrict__ p1,
                         const float* __restrict__ p2) {
    int idx = blockIdx.x * blockDim.x + threadIdx.x;
    if (idx >= BB * NN) return;
    int b = idx / NN, n = idx - b * NN;
    int lvl, HW, local; float cx, cy;
    locate(n, lvl, HW, local, cx, cy);
    const float* p = (lvl == 0) ? p0 : ((lvl == 1) ? p1 : p2);
    float strideF = (lvl == 0) ? 8.0f : ((lvl == 1) ? 16.0f : 32.0f);
    const float* base = p + (size_t)b * 144 * HW + local;
    float d[4];
#pragma unroll
    for (int k = 0; k < 4; k++) {
        float v[16]; float mx = -1e30f;
#pragma unroll
        for (int j = 0; j < 16; j++) {
            v[j] = base[(size_t)(k * 16 + j) * HW];
            mx = fmaxf(mx, v[j]);
        }
        float s = 0.f, dot = 0.f;
#pragma unroll
        for (int j = 0; j < 16; j++) {
            float e = expf(v[j] - mx);
            s += e; dot += e * (float)j;
        }
        d[k] = (dot / s) * strideF;
    }
    float* ob = g_boxes + (size_t)idx * 4;
    ob[0] = cx - d[0]; ob[1] = cy - d[1]; ob[2] = cx + d[2]; ob[3] = cy + d[3];
}

// ---------------- k_bce: dense BCE base term over cls channels ----------------
__global__ void k_bce(const float* __restrict__ p, int HW) {
    long long total = (long long)BB * CC * HW;
    long long stride = (long long)gridDim.x * blockDim.x;
    float local = 0.f;
    for (long long i = (long long)blockIdx.x * blockDim.x + threadIdx.x; i < total; i += stride) {
        long long b = i / ((long long)CC * HW);
        long long r = i - b * ((long long)CC * HW);
        float s = p[b * 144 * HW + (long long)64 * HW + r];
        local += fmaxf(s, 0.f) + log1pf(expf(-fabsf(s)));
    }
    __shared__ float sred[256];
    sred[threadIdx.x] = local;
    __syncthreads();
    for (int s = 128; s > 0; s >>= 1) {
        if (threadIdx.x < s) sred[threadIdx.x] += sred[threadIdx.x + s];
        __syncthreads();
    }
    if (threadIdx.x == 0) atomicAdd(&g_bce, (double)sred[0]);
}

// ---------------- k_align: pairwise iou + align metric per (b,g) ----------------
__global__ void k_align(const float* __restrict__ p0,
                        const float* __restrict__ p1,
                        const float* __restrict__ p2,
                        const float* __restrict__ gt,
                        const int* __restrict__ lab) {
    int bg = blockIdx.x;            // b*GG + g
    int b = bg / GG;
    float x1 = gt[(size_t)bg * 4 + 0], y1 = gt[(size_t)bg * 4 + 1];
    float x2 = gt[(size_t)bg * 4 + 2], y2 = gt[(size_t)bg * 4 + 3];
    bool mgt = (x1 + y1 + x2 + y2) > 0.f;
    int label = lab[bg];
    float ag = fmaxf(x2 - x1, 0.f) * fmaxf(y2 - y1, 0.f);
    for (int n = threadIdx.x; n < NN; n += blockDim.x) {
        int lvl, HW, local; float cx, cy;
        locate(n, lvl, HW, local, cx, cy);
        const float* pb = g_boxes + ((size_t)b * NN + n) * 4;
        float px1 = pb[0], py1 = pb[1], px2 = pb[2], py2 = pb[3];
        float iw = fminf(x2, px2) - fmaxf(x1, px1);
        float ih = fminf(y2, py2) - fmaxf(y1, py1);
        iw = fmaxf(iw, 0.f); ih = fmaxf(ih, 0.f);
        float inter = iw * ih;
        float ap = fmaxf(px2 - px1, 0.f) * fmaxf(py2 - py1, 0.f);
        float iou = inter / ((ag + ap) - inter + 1e-7f);
        bool ing = (cx > x1) && (cx < x2) && (cy > y1) && (cy < y2);
        float align = 0.f;
        if (ing && mgt) {
            const float* p = (lvl == 0) ? p0 : ((lvl == 1) ? p1 : p2);
            float s = p[(size_t)b * 144 * HW + (size_t)(64 + label) * HW + local];
            float prob = 1.f / (1.f + expf(-s));
            float i2 = iou * iou;
            align = sqrtf(prob) * (i2 * i2 * i2);
        }
        g_iou[(size_t)bg * NN + n] = iou;
        g_align[(size_t)bg * NN + n] = align;
    }
}

// ---------------- k_topk: per (b,g) top-10 of align ----------------
__global__ void k_topk() {
    int bg = blockIdx.x;
    const float* row = g_align + (size_t)bg * NN;
    float lv[TKK]; int lidx[TKK];
#pragma unroll
    for (int j = 0; j < TKK; j++) { lv[j] = -1.0f; lidx[j] = 0x7FFFFFFF; }
    float vmin = -1.0f;
    for (int n = threadIdx.x; n < NN; n += blockDim.x) {
        float v = row[n];
        if (v > vmin) {
            int j = TKK - 1;
            while (j > 0 && v > lv[j - 1]) { lv[j] = lv[j - 1]; lidx[j] = lidx[j - 1]; j--; }
            lv[j] = v; lidx[j] = n;
            vmin = lv[TKK - 1];
        }
    }
    __shared__ float sv[256];
    __shared__ int si[256];
    int ptr = 0;
    for (int r = 0; r < TKK; r++) {
        float cv = (ptr < TKK) ? lv[ptr] : -2.0f;
        int ci = (ptr < TKK) ? lidx[ptr] : 0x7FFFFFFF;
        sv[threadIdx.x] = cv; si[threadIdx.x] = ci;
        __syncthreads();
        for (int s = 128; s > 0; s >>= 1) {
            if (threadIdx.x < s) {
                float v2 = sv[threadIdx.x + s]; int i2 = si[threadIdx.x + s];
                if (v2 > sv[threadIdx.x] ||
                    (v2 == sv[threadIdx.x] && i2 < si[threadIdx.x])) {
                    sv[threadIdx.x] = v2; si[threadIdx.x] = i2;
                }
            }
            __syncthreads();
        }
        float bestv = sv[0]; int besti = si[0];
        if (threadIdx.x == 0)
            g_topk[bg * TKK + r] = (bestv > EPSF) ? besti : -1;
        if (ptr < TKK && lidx[ptr] == besti && lv[ptr] == bestv) ptr++;
        __syncthreads();
    }
}

// ---------------- k_select: resolve assignments per anchor ----------------
__global__ void k_select() {
    __shared__ int s_topk[GG * TKK];
    int b = blockIdx.y;
    for (int i = threadIdx.x; i < GG * TKK; i += blockDim.x)
        s_topk[i] = g_topk[b * GG * TKK + i];
    __syncthreads();
    int n = blockIdx.x * blockDim.x + threadIdx.x;
    if (n >= NN) return;
    int count = 0, first = -1;
#pragma unroll
    for (int g = 0; g < GG; g++) {
        bool m = false;
#pragma unroll
        for (int j = 0; j < TKK; j++) m = m || (s_topk[g * TKK + j] == n);
        if (m) { count++; if (first < 0) first = g; }
    }
    // best_gt = argmax_g iou (first max)
    float bi = -1.f; int bgidx = 0;
#pragma unroll
    for (int g = 0; g < GG; g++) {
        float v = g_iou[((size_t)b * GG + g) * NN + n];
        if (v > bi) { bi = v; bgidx = g; }
    }
    int matched; unsigned char fg;
    if (count > 1)      { fg = 1; matched = bgidx; }
    else if (count == 1){ fg = 1; matched = first; }
    else                { fg = 0; matched = 0; }
    int idx = b * NN + n;
    g_fg[idx] = fg; g_matched[idx] = matched;
    if (fg) {
        float a = g_align[((size_t)b * GG + matched) * NN + n];
        float io = g_iou[((size_t)b * GG + matched) * NN + n];
        g_alignat[idx] = a;
        atomicMax(&g_posA[b * GG + matched], __float_as_uint(a));
        atomicMax(&g_posI[b * GG + matched], __float_as_uint(io));
        atomicAdd(&g_fgcnt, 1);
    }
}

// ---------------- k_loss: fg-sparse CIoU + BCE cross term + DFL loss ----------------
__global__ void k_loss(const float* __restrict__ p0,
                       const float* __restrict__ p1,
                       const float* __restrict__ p2,
                       const float* __restrict__ gt,
                       const int* __restrict__ lab) {
    int n = blockIdx.x * blockDim.x + threadIdx.x;
    int b = blockIdx.y;
    if (n >= NN) return;
    int idx = b * NN + n;
    if (!g_fg[idx]) return;
    int mg = g_matched[idx];
    const float* tb = gt + ((size_t)b * GG + mg) * 4;
    float tx1 = tb[0], ty1 = tb[1], tx2 = tb[2], ty2 = tb[3];
    const float* pb = g_boxes + (size_t)idx * 4;
    float px1 = pb[0], py1 = pb[1], px2 = pb[2], py2 = pb[3];

    // CIoU (eps = 1e-7)
    float w1 = px2 - px1, h1 = py2 - py1;
    float w2 = tx2 - tx1, h2 = ty2 - ty1;
    float iw = fmaxf(fminf(px2, tx2) - fmaxf(px1, tx1), 0.f);
    float ih = fmaxf(fminf(py2, ty2) - fmaxf(py1, ty1), 0.f);
    float inter = iw * ih;
    float uni = w1 * h1 + w2 * h2 - inter + 1e-7f;
    float iou = inter / uni;
    float cw = fmaxf(px2, tx2) - fminf(px1, tx1);
    float ch = fmaxf(py2, ty2) - fminf(py1, ty1);
    float c2 = cw * cw + ch * ch + 1e-7f;
    float dxs = px1 + px2 - tx1 - tx2;
    float dys = py1 + py2 - ty1 - ty2;
    float rho2 = (dxs * dxs + dys * dys) * 0.25f;
    float dv = atanf(w2 / (h2 + 1e-7f)) - atanf(w1 / (h1 + 1e-7f));
    const float c4pi2 = 4.0f / (3.14159265358979323846f * 3.14159265358979323846f);
    float v = c4pi2 * dv * dv;
    float alpha = v / (v - iou + 1.0f + 1e-7f);
    float ciou = iou - rho2 / c2 - alpha * v;
    float liou = 1.f - ciou;

    // normalization (target score)
    float a = g_alignat[idx];
    float pA = __uint_as_float(g_posA[b * GG + mg]);
    float pI = __uint_as_float(g_posI[b * GG + mg]);
    float norm = a * pI / (pA + EPSF);

    int lvl, HW, local; float cx, cy;
    locate(n, lvl, HW, local, cx, cy);
    const float* p = (lvl == 0) ? p0 : ((lvl == 1) ? p1 : p2);
    int label = lab[b * GG + mg];
    float s = p[(size_t)b * 144 * HW + (size_t)(64 + label) * HW + local];
    float cross = s * norm;

    // DFL loss (two-hot targets against log-softmax over 16 bins, 4 sides)
    float ds[4] = { fmaxf(cx - tx1, 0.f), fmaxf(cy - ty1, 0.f),
                    fmaxf(tx2 - cx, 0.f), fmaxf(ty2 - cy, 0.f) };
    float ldfl = 0.f;
    const float* dbase = p + (size_t)b * 144 * HW + local;
#pragma unroll
    for (int k = 0; k < 4; k++) {
        float tbv = fminf(ds[k], 14.999999f);
        int li = (int)tbv;               // floor (nonneg)
        float aa = tbv - (float)li;
        int ui = min(li + 1, 15);
        float vv[16]; float mx = -1e30f;
#pragma unroll
        for (int j = 0; j < 16; j++) {
            vv[j] = dbase[(size_t)(k * 16 + j) * HW];
            mx = fmaxf(mx, vv[j]);
        }
        float se = 0.f;
#pragma unroll
        for (int j = 0; j < 16; j++) se += expf(vv[j] - mx);
        float lse = logf(se) + mx;
        ldfl += -((1.f - aa) * (vv[li] - lse) + aa * (vv[ui] - lse));
    }

    atomicAdd(&g_iou_sum, (double)liou);
    atomicAdd(&g_cross_sum, (double)cross);
    atomicAdd(&g_dfl_sum, (double)ldfl);
}

// ---------------- k_final ----------------
__global__ void k_final(float* __restrict__ out) {
    double np = (double)g_fgcnt;
    if (np < 1.0) np = 1.0;
    out[0] = (float)(7.5 * g_iou_sum / np);
    out[1] = (float)(0.5 * (g_bce - g_cross_sum) / np);
    out[2] = (float)(1.5 * g_dfl_sum / np);
}

// ---------------- launch ----------------
extern "C" void kernel_launch(void* const* d_in, const int* in_sizes, int n_in,
                              void* d_out, int out_size) {
    const float* p0 = (const float*)d_in[0];
    const float* p1 = (const float*)d_in[1];
    const float* p2 = (const float*)d_in[2];
    const float* gt = (const float*)d_in[3];
    const int* lab = (const int*)d_in[4];
    float* out = (float*)d_out;

    k_init<<<4, 256>>>();
    k_decode<<<(BB * NN + 255) / 256, 256>>>(p0, p1, p2);
    k_bce<<<2048, 256>>>(p0, 6400);
    k_bce<<<1024, 256>>>(p1, 1600);
    k_bce<<<512, 256>>>(p2, 400);
    k_align<<<BB * GG, 256>>>(p0, p1, p2, gt, lab);
    k_topk<<<BB * GG, 256>>>();
    {
        dim3 gsel((NN + 255) / 256, BB);
        k_select<<<gsel, 256>>>();
        k_loss<<<gsel, 256>>>(p0, p1, p2, gt, lab);
    }
    k_final<<<1, 1>>>(out);
}

// round 2
// speedup vs baseline: 1.7895x; 1.7895x over previous
#include <cuda_runtime.h>
#include <math.h>
#include <stdint.h>

#define BB 32
#define GG 32
#define NN 8400
#define CC 80
#define TKK 10
#define EPSF 1e-9f

// ---------------- scratch (device globals; no allocs allowed) ----------------
__device__ float g_boxes[BB * NN * 4];          // 4.3 MB (only big scratch left)
__device__ int g_topk[BB * GG * TKK];
__device__ unsigned int g_posA[BB * GG];        // float bits, atomicMax (nonneg)
__device__ unsigned int g_posI[BB * GG];
__device__ double g_SA[BB * GG];                // sum of s*align per (b,g)
__device__ int g_fgcnt;
__device__ double g_bce;
__device__ double g_iou_sum;
__device__ double g_dfl_sum;

// ---------------- helpers ----------------
__device__ __forceinline__ void locate(int n, int& lvl, int& HW, int& local,
                                       float& cx, float& cy) {
    if (n < 6400) {
        lvl = 0; HW = 6400; local = n;
        int y = n / 80; int x = n - y * 80;
        cx = (x + 0.5f) * 8.0f; cy = (y + 0.5f) * 8.0f;
    } else if (n < 8000) {
        lvl = 1; HW = 1600; local = n - 6400;
        int y = local / 40; int x = local - y * 40;
        cx = (x + 0.5f) * 16.0f; cy = (y + 0.5f) * 16.0f;
    } else {
        lvl = 2; HW = 400; local = n - 8000;
        int y = local / 20; int x = local - y * 20;
        cx = (x + 0.5f) * 32.0f; cy = (y + 0.5f) * 32.0f;
    }
}

__device__ __forceinline__ float iou_gt_pred(float x1, float y1, float x2, float y2,
                                             float ag,
                                             float px1, float py1, float px2, float py2) {
    float iw = fmaxf(fminf(x2, px2) - fmaxf(x1, px1), 0.f);
    float ih = fmaxf(fminf(y2, py2) - fmaxf(y1, py1), 0.f);
    float inter = iw * ih;
    float ap = fmaxf(px2 - px1, 0.f) * fmaxf(py2 - py1, 0.f);
    return inter / ((ag + ap) - inter + 1e-7f);
}

// ---------------- k_init ----------------
__global__ void k_init() {
    int i = blockIdx.x * blockDim.x + threadIdx.x;
    if (i < BB * GG) { g_posA[i] = 0u; g_posI[i] = 0u; g_SA[i] = 0.0; }
    if (i == 0) { g_fgcnt = 0; g_bce = 0.0; g_iou_sum = 0.0; g_dfl_sum = 0.0; }
}

// ---------------- k_decode_bce: DFL decode + dense BCE base term, one pass ----------------
__global__ void k_decode_bce(const float* __restrict__ p0,
                             const float* __restrict__ p1,
                             const float* __restrict__ p2) {
    int n = blockIdx.x * blockDim.x + threadIdx.x;
    int b = blockIdx.y;
    float acc = 0.f;
    if (n < NN) {
        int lvl, HW, local; float cx, cy;
        locate(n, lvl, HW, local, cx, cy);
        const float* p = (lvl == 0) ? p0 : ((lvl == 1) ? p1 : p2);
        float strideF = (lvl == 0) ? 8.0f : ((lvl == 1) ? 16.0f : 32.0f);
        const float* base = p + (size_t)b * 144 * HW + local;
        float d[4];
#pragma unroll
        for (int k = 0; k < 4; k++) {
            float s = 0.f, dot = 0.f;
#pragma unroll
            for (int j = 0; j < 16; j++) {
                // logits ~N(0,1): direct exp is safe, no max-subtraction needed
                float e = __expf(base[(size_t)(k * 16 + j) * HW]);
                s += e; dot += e * (float)j;
            }
            d[k] = __fdividef(dot, s) * strideF;
        }
        float4 ob = make_float4(cx - d[0], cy - d[1], cx + d[2], cy + d[3]);
        *reinterpret_cast<float4*>(g_boxes + ((size_t)b * NN + n) * 4) = ob;

        const float* cb = base + (size_t)64 * HW;
#pragma unroll 10
        for (int c = 0; c < CC; c++) {
            float s = cb[(size_t)c * HW];
            acc += fmaxf(s, 0.f) + __logf(1.f + __expf(-fabsf(s)));
        }
    }
    __shared__ float sred[256];
    sred[threadIdx.x] = acc;
    __syncthreads();
    for (int s = 128; s > 0; s >>= 1) {
        if (threadIdx.x < s) sred[threadIdx.x] += sred[threadIdx.x + s];
        __syncthreads();
    }
    if (threadIdx.x == 0) atomicAdd(&g_bce, (double)sred[0]);
}

// ---------------- k_align_topk: per (b,g), align on-the-fly -> top-10 indices ----------------
__global__ void k_align_topk(const float* __restrict__ p0,
                             const float* __restrict__ p1,
                             const float* __restrict__ p2,
                             const float* __restrict__ gt,
                             const int* __restrict__ lab) {
    int bg = blockIdx.x;            // b*GG + g
    int b = bg >> 5;
    float4 G = *reinterpret_cast<const float4*>(gt + (size_t)bg * 4);
    float x1 = G.x, y1 = G.y, x2 = G.z, y2 = G.w;
    bool mgt = (x1 + y1 + x2 + y2) > 0.f;
    int label = lab[bg];
    float ag = fmaxf(x2 - x1, 0.f) * fmaxf(y2 - y1, 0.f);

    float lv[TKK]; int lidx[TKK];
#pragma unroll
    for (int j = 0; j < TKK; j++) { lv[j] = -1.0f; lidx[j] = 0x7FFFFFFF; }
    float vmin = -1.0f;

    for (int n = threadIdx.x; n < NN; n += blockDim.x) {
        int lvl, HW, local; float cx, cy;
        locate(n, lvl, HW, local, cx, cy);
        bool ing = (cx > x1) && (cx < x2) && (cy > y1) && (cy < y2);
        if (ing && mgt) {
            float4 pb = *reinterpret_cast<const float4*>(g_boxes + ((size_t)b * NN + n) * 4);
            float iou = iou_gt_pred(x1, y1, x2, y2, ag, pb.x, pb.y, pb.z, pb.w);
            const float* p = (lvl == 0) ? p0 : ((lvl == 1) ? p1 : p2);
            float sc = p[(size_t)b * 144 * HW + (size_t)(64 + label) * HW + local];
            float prob = __fdividef(1.f, 1.f + __expf(-sc));
            float i2 = iou * iou;
            float align = sqrtf(prob) * (i2 * i2 * i2);
            if (align > vmin && align > EPSF) {
                int j = TKK - 1;
                while (j > 0 && align > lv[j - 1]) { lv[j] = lv[j - 1]; lidx[j] = lidx[j - 1]; j--; }
                lv[j] = align; lidx[j] = n;
                vmin = lv[TKK - 1];
            }
        }
    }

    __shared__ float sv[256];
    __shared__ int si[256];
    int ptr = 0;
    for (int r = 0; r < TKK; r++) {
        float cv = (ptr < TKK) ? lv[ptr] : -2.0f;
        int ci = (ptr < TKK) ? lidx[ptr] : 0x7FFFFFFF;
        sv[threadIdx.x] = cv; si[threadIdx.x] = ci;
        __syncthreads();
        for (int s = 128; s > 0; s >>= 1) {
            if (threadIdx.x < s) {
                float v2 = sv[threadIdx.x + s]; int i2 = si[threadIdx.x + s];
                if (v2 > sv[threadIdx.x] ||
                    (v2 == sv[threadIdx.x] && i2 < si[threadIdx.x])) {
                    sv[threadIdx.x] = v2; si[threadIdx.x] = i2;
                }
            }
            __syncthreads();
        }
        float bestv = sv[0]; int besti = si[0];
        if (threadIdx.x == 0)
            g_topk[bg * TKK + r] = (bestv > EPSF) ? besti : -1;
        if (ptr < TKK && lidx[ptr] == besti && lv[ptr] == bestv) ptr++;
        __syncthreads();
    }
}

// ---------------- k_select: resolve assignment + CIoU + DFL loss, all fused ----------------
__global__ void k_select(const float* __restrict__ p0,
                         const float* __restrict__ p1,
                         const float* __restrict__ p2,
                         const float* __restrict__ gt,
                         const int* __restrict__ lab) {
    __shared__ int s_topk[GG * TKK];
    __shared__ float4 s_gt[GG];
    __shared__ int s_lab[GG];
    int b = blockIdx.y;
    for (int i = threadIdx.x; i < GG * TKK; i += blockDim.x)
        s_topk[i] = g_topk[b * GG * TKK + i];
    if (threadIdx.x < GG) {
        s_gt[threadIdx.x] = *reinterpret_cast<const float4*>(gt + ((size_t)b * GG + threadIdx.x) * 4);
        s_lab[threadIdx.x] = lab[b * GG + threadIdx.x];
    }
    __syncthreads();

    int n = blockIdx.x * blockDim.x + threadIdx.x;
    float liou = 0.f, ldfl = 0.f;
    int fgflag = 0;

    if (n < NN) {
        int lvl, HW, local; float cx, cy;
        locate(n, lvl, HW, local, cx, cy);
        float4 pb = *reinterpret_cast<const float4*>(g_boxes + ((size_t)b * NN + n) * 4);

        int count = 0, first = -1;
        float bi = -1.f; int bgi = 0;
        for (int g = 0; g < GG; g++) {
            bool m = false;
#pragma unroll
            for (int j = 0; j < TKK; j++) m = m || (s_topk[g * TKK + j] == n);
            if (m) { count++; if (first < 0) first = g; }
            float4 G = s_gt[g];
            float ag = fmaxf(G.z - G.x, 0.f) * fmaxf(G.w - G.y, 0.f);
            float iou = iou_gt_pred(G.x, G.y, G.z, G.w, ag, pb.x, pb.y, pb.z, pb.w);
            if (iou > bi) { bi = iou; bgi = g; }
        }

        if (count > 0) {
            fgflag = 1;
            int mg = (count > 1) ? bgi : first;
            float4 G = s_gt[mg];
            float tx1 = G.x, ty1 = G.y, tx2 = G.z, ty2 = G.w;
            float ag = fmaxf(tx2 - tx1, 0.f) * fmaxf(ty2 - ty1, 0.f);
            float iou_m = iou_gt_pred(tx1, ty1, tx2, ty2, ag, pb.x, pb.y, pb.z, pb.w);
            bool mgt = (tx1 + ty1 + tx2 + ty2) > 0.f;
            bool ing = (cx > tx1) && (cx < tx2) && (cy > ty1) && (cy < ty2);

            const float* p = (lvl == 0) ? p0 : ((lvl == 1) ? p1 : p2);
            const float* dbase = p + (size_t)b * 144 * HW + local;

            float a = 0.f;
            if (ing && mgt) {
                int label = s_lab[mg];
                float sc = dbase[(size_t)(64 + label) * HW];
                float prob = __fdividef(1.f, 1.f + __expf(-sc));
                float i2 = iou_m * iou_m;
                a = sqrtf(prob) * (i2 * i2 * i2);
                if (a > 0.f)
                    atomicAdd(&g_SA[b * GG + mg], (double)(sc * a));
            }
            atomicMax(&g_posA[b * GG + mg], __float_as_uint(a));
            atomicMax(&g_posI[b * GG + mg], __float_as_uint(iou_m));

            // CIoU loss
            float px1 = pb.x, py1 = pb.y, px2 = pb.z, py2 = pb.w;
            float w1 = px2 - px1, h1 = py2 - py1;
            float w2 = tx2 - tx1, h2 = ty2 - ty1;
            float iw = fmaxf(fminf(px2, tx2) - fmaxf(px1, tx1), 0.f);
            float ih = fmaxf(fminf(py2, ty2) - fmaxf(py1, ty1), 0.f);
            float inter = iw * ih;
            float uni = w1 * h1 + w2 * h2 - inter + 1e-7f;
            float iou = inter / uni;
            float cw = fmaxf(px2, tx2) - fminf(px1, tx1);
            float ch = fmaxf(py2, ty2) - fminf(py1, ty1);
            float c2 = cw * cw + ch * ch + 1e-7f;
            float dxs = px1 + px2 - tx1 - tx2;
            float dys = py1 + py2 - ty1 - ty2;
            float rho2 = (dxs * dxs + dys * dys) * 0.25f;
            float dv = atanf(w2 / (h2 + 1e-7f)) - atanf(w1 / (h1 + 1e-7f));
            const float c4pi2 = 4.0f / (3.14159265358979323846f * 3.14159265358979323846f);
            float v = c4pi2 * dv * dv;
            float alpha = v / (v - iou + 1.0f + 1e-7f);
            liou = 1.f - (iou - rho2 / c2 - alpha * v);

            // DFL loss (two-hot vs log-softmax, 4 sides x 16 bins)
            float ds[4] = { fmaxf(cx - tx1, 0.f), fmaxf(cy - ty1, 0.f),
                            fmaxf(tx2 - cx, 0.f), fmaxf(ty2 - cy, 0.f) };
#pragma unroll
            for (int k = 0; k < 4; k++) {
                float tbv = fminf(ds[k], 14.999999f);
                int li = (int)tbv;
                float aa = tbv - (float)li;
                int ui = min(li + 1, 15);
                float vv[16]; float mx = -1e30f;
#pragma unroll
                for (int j = 0; j < 16; j++) {
                    vv[j] = dbase[(size_t)(k * 16 + j) * HW];
                    mx = fmaxf(mx, vv[j]);
                }
                float se = 0.f;
#pragma unroll
                for (int j = 0; j < 16; j++) se += __expf(vv[j] - mx);
                float lse = __logf(se) + mx;
                ldfl += -((1.f - aa) * (vv[li] - lse) + aa * (vv[ui] - lse));
            }
        }
    }

    // warp-aggregated fg count
    unsigned msk = __ballot_sync(0xffffffffu, fgflag);
    if ((threadIdx.x & 31) == 0 && msk) atomicAdd(&g_fgcnt, (int)__popc(msk));

    // block reduce the two loss partials
    __shared__ float r1[256], r2[256];
    r1[threadIdx.x] = liou; r2[threadIdx.x] = ldfl;
    __syncthreads();
    for (int s = 128; s > 0; s >>= 1) {
        if (threadIdx.x < s) {
            r1[threadIdx.x] += r1[threadIdx.x + s];
            r2[threadIdx.x] += r2[threadIdx.x + s];
        }
        __syncthreads();
    }
    if (threadIdx.x == 0) {
        if (r1[0] != 0.f) atomicAdd(&g_iou_sum, (double)r1[0]);
        if (r2[0] != 0.f) atomicAdd(&g_dfl_sum, (double)r2[0]);
    }
}

// ---------------- k_final: cross term + outputs ----------------
__global__ void k_final(float* __restrict__ out) {
    __shared__ double sred[256];
    double c = 0.0;
    for (int i = threadIdx.x; i < BB * GG; i += 256) {
        float pA = __uint_as_float(g_posA[i]);
        float pI = __uint_as_float(g_posI[i]);
        c += g_SA[i] * (double)(pI / (pA + EPSF));
    }
    sred[threadIdx.x] = c;
    __syncthreads();
    for (int s = 128; s > 0; s >>= 1) {
        if (threadIdx.x < s) sred[threadIdx.x] += sred[threadIdx.x + s];
        __syncthreads();
    }
    if (threadIdx.x == 0) {
        double np = (double)g_fgcnt;
        if (np < 1.0) np = 1.0;
        out[0] = (float)(7.5 * g_iou_sum / np);
        out[1] = (float)(0.5 * (g_bce - sred[0]) / np);
        out[2] = (float)(1.5 * g_dfl_sum / np);
    }
}

// ---------------- launch ----------------
extern "C" void kernel_launch(void* const* d_in, const int* in_sizes, int n_in,
                              void* d_out, int out_size) {
    const float* p0 = (const float*)d_in[0];
    const float* p1 = (const float*)d_in[1];
    const float* p2 = (const float*)d_in[2];
    const float* gt = (const float*)d_in[3];
    const int* lab = (const int*)d_in[4];
    float* out = (float*)d_out;

    dim3 gbn((NN + 255) / 256, BB);
    k_init<<<4, 256>>>();
    k_decode_bce<<<gbn, 256>>>(p0, p1, p2);
    k_align_topk<<<BB * GG, 256>>>(p0, p1, p2, gt, lab);
    k_select<<<gbn, 256>>>(p0, p1, p2, gt, lab);
    k_final<<<1, 256>>>(out);
}

// round 3
// speedup vs baseline: 2.9228x; 1.6334x over previous
#include <cuda_runtime.h>
#include <math.h>
#include <stdint.h>

#define BB 32
#define GG 32
#define NN 8400
#define CC 80
#define TKK 10
#define EPSF 1e-9f

// ---------------- scratch (device globals; no allocs allowed) ----------------
__device__ float g_boxes[BB * NN * 4];          // 4.3 MB
__device__ unsigned int g_mask[BB * NN];        // per-anchor GT bitmask (1.05 MB)
__device__ unsigned int g_posA[BB * GG];        // float bits, atomicMax (nonneg)
__device__ unsigned int g_posI[BB * GG];
__device__ double g_SA[BB * GG];                // sum of s*align per (b,g)
__device__ int g_fgcnt;
__device__ double g_bce;
__device__ double g_iou_sum;
__device__ double g_dfl_sum;

// ---------------- helpers ----------------
__device__ __forceinline__ void locate(int n, int& lvl, int& HW, int& local,
                                       float& cx, float& cy) {
    if (n < 6400) {
        lvl = 0; HW = 6400; local = n;
        int y = n / 80; int x = n - y * 80;
        cx = (x + 0.5f) * 8.0f; cy = (y + 0.5f) * 8.0f;
    } else if (n < 8000) {
        lvl = 1; HW = 1600; local = n - 6400;
        int y = local / 40; int x = local - y * 40;
        cx = (x + 0.5f) * 16.0f; cy = (y + 0.5f) * 16.0f;
    } else {
        lvl = 2; HW = 400; local = n - 8000;
        int y = local / 20; int x = local - y * 20;
        cx = (x + 0.5f) * 32.0f; cy = (y + 0.5f) * 32.0f;
    }
}

__device__ __forceinline__ float iou_gt_pred(float x1, float y1, float x2, float y2,
                                             float ag,
                                             float px1, float py1, float px2, float py2) {
    float iw = fmaxf(fminf(x2, px2) - fmaxf(x1, px1), 0.f);
    float ih = fmaxf(fminf(y2, py2) - fmaxf(y1, py1), 0.f);
    float inter = iw * ih;
    float ap = fmaxf(px2 - px1, 0.f) * fmaxf(py2 - py1, 0.f);
    return inter / ((ag + ap) - inter + 1e-7f);
}

// ---------------- k_init: zero accumulators + anchor mask ----------------
__global__ void k_init() {
    int i = blockIdx.x * blockDim.x + threadIdx.x;
    if (i < BB * NN) g_mask[i] = 0u;
    if (i < BB * GG) { g_posA[i] = 0u; g_posI[i] = 0u; g_SA[i] = 0.0; }
    if (i == 0) { g_fgcnt = 0; g_bce = 0.0; g_iou_sum = 0.0; g_dfl_sum = 0.0; }
}

// ---------------- k_decode_bce: 4 anchors/thread, float4 loads ----------------
__global__ void k_decode_bce(const float* __restrict__ p0,
                             const float* __restrict__ p1,
                             const float* __restrict__ p2) {
    int q = blockIdx.x * blockDim.x + threadIdx.x;   // quad index
    int b = blockIdx.y;
    float acc = 0.f;
    if (q < NN / 4) {
        int n0 = q * 4;
        int lvl, HW, local; float cx0, cy0;
        locate(n0, lvl, HW, local, cx0, cy0);
        const float* p = (lvl == 0) ? p0 : ((lvl == 1) ? p1 : p2);
        float strideF = (lvl == 0) ? 8.0f : ((lvl == 1) ? 16.0f : 32.0f);
        const float* base = p + (size_t)b * 144 * HW + local;

        float dist[4][4];   // [side][anchor-in-quad]
#pragma unroll
        for (int k = 0; k < 4; k++) {
            float s0 = 0.f, s1 = 0.f, s2 = 0.f, s3 = 0.f;
            float d0 = 0.f, d1 = 0.f, d2 = 0.f, d3 = 0.f;
#pragma unroll
            for (int j = 0; j < 16; j++) {
                float4 v = *reinterpret_cast<const float4*>(base + (size_t)(k * 16 + j) * HW);
                float e0 = __expf(v.x), e1 = __expf(v.y), e2 = __expf(v.z), e3 = __expf(v.w);
                float fj = (float)j;
                s0 += e0; s1 += e1; s2 += e2; s3 += e3;
                d0 += e0 * fj; d1 += e1 * fj; d2 += e2 * fj; d3 += e3 * fj;
            }
            dist[k][0] = __fdividef(d0, s0) * strideF;
            dist[k][1] = __fdividef(d1, s1) * strideF;
            dist[k][2] = __fdividef(d2, s2) * strideF;
            dist[k][3] = __fdividef(d3, s3) * strideF;
        }
        float4* ob = reinterpret_cast<float4*>(g_boxes + ((size_t)b * NN + n0) * 4);
#pragma unroll
        for (int i = 0; i < 4; i++) {
            float cxi = cx0 + (float)i * strideF;
            ob[i] = make_float4(cxi - dist[0][i], cy0 - dist[1][i],
                                cxi + dist[2][i], cy0 + dist[3][i]);
        }

        // BCE base term: softplus over 80 cls channels, logs batched 16 at a time
        const float* cb = base + (size_t)64 * HW;
        float pr0 = 1.f, pr1 = 1.f, pr2 = 1.f, pr3 = 1.f;
#pragma unroll 8
        for (int c = 0; c < CC; c++) {
            float4 v = *reinterpret_cast<const float4*>(cb + (size_t)c * HW);
            acc += fmaxf(v.x, 0.f) + fmaxf(v.y, 0.f) + fmaxf(v.z, 0.f) + fmaxf(v.w, 0.f);
            pr0 *= 1.f + __expf(-fabsf(v.x));
            pr1 *= 1.f + __expf(-fabsf(v.y));
            pr2 *= 1.f + __expf(-fabsf(v.z));
            pr3 *= 1.f + __expf(-fabsf(v.w));
            if ((c & 15) == 15) {
                acc += __logf(pr0) + __logf(pr1) + __logf(pr2) + __logf(pr3);
                pr0 = pr1 = pr2 = pr3 = 1.f;
            }
        }
    }
    __shared__ float sred[128];
    sred[threadIdx.x] = acc;
    __syncthreads();
    for (int s = 64; s > 0; s >>= 1) {
        if (threadIdx.x < s) sred[threadIdx.x] += sred[threadIdx.x + s];
        __syncthreads();
    }
    if (threadIdx.x == 0) atomicAdd(&g_bce, (double)sred[0]);
}

// ---------------- k_align_topk: box-bounded candidate scan -> top-10 -> mask scatter ----------------
__global__ void k_align_topk(const float* __restrict__ p0,
                             const float* __restrict__ p1,
                             const float* __restrict__ p2,
                             const float* __restrict__ gt,
                             const int* __restrict__ lab) {
    int bg = blockIdx.x;            // b*GG + g
    int b = bg >> 5;
    int gidx = bg & 31;
    float4 G = *reinterpret_cast<const float4*>(gt + (size_t)bg * 4);
    float x1 = G.x, y1 = G.y, x2 = G.z, y2 = G.w;
    bool mgt = (x1 + y1 + x2 + y2) > 0.f;
    int label = lab[bg];
    float ag = fmaxf(x2 - x1, 0.f) * fmaxf(y2 - y1, 0.f);

    float lv[TKK]; int lidx[TKK];
#pragma unroll
    for (int j = 0; j < TKK; j++) { lv[j] = -1.0f; lidx[j] = 0x7FFFFFFF; }
    float vmin = -1.0f;

    if (mgt) {
#pragma unroll
        for (int lvl = 0; lvl < 3; lvl++) {
            float sF = (lvl == 0) ? 8.0f : ((lvl == 1) ? 16.0f : 32.0f);
            int D = (lvl == 0) ? 80 : ((lvl == 1) ? 40 : 20);
            int HW = D * D;
            int nbase = (lvl == 0) ? 0 : ((lvl == 1) ? 6400 : 8000);
            const float* p = (lvl == 0) ? p0 : ((lvl == 1) ? p1 : p2);
            const float* cls = p + (size_t)b * 144 * HW + (size_t)(64 + label) * HW;

            float inv = 1.0f / sF;
            int x_lo = max(0, (int)floorf(x1 * inv - 0.5f));
            int x_hi = min(D - 1, (int)ceilf(x2 * inv - 0.5f));
            int y_lo = max(0, (int)floorf(y1 * inv - 0.5f));
            int y_hi = min(D - 1, (int)ceilf(y2 * inv - 0.5f));
            if (x_hi < x_lo || y_hi < y_lo) continue;
            int nx = x_hi - x_lo + 1;
            int tot = nx * (y_hi - y_lo + 1);

            for (int t = threadIdx.x; t < tot; t += blockDim.x) {
                int yy = y_lo + t / nx;
                int xx = x_lo + t - (t / nx) * nx;
                float cx = (xx + 0.5f) * sF, cy = (yy + 0.5f) * sF;
                if (cx > x1 && cx < x2 && cy > y1 && cy < y2) {
                    int local = yy * D + xx;
                    int n = nbase + local;
                    float4 pb = *reinterpret_cast<const float4*>(g_boxes + ((size_t)b * NN + n) * 4);
                    float iou = iou_gt_pred(x1, y1, x2, y2, ag, pb.x, pb.y, pb.z, pb.w);
                    float sc = cls[local];
                    float prob = __fdividef(1.f, 1.f + __expf(-sc));
                    float i2 = iou * iou;
                    float align = sqrtf(prob) * (i2 * i2 * i2);
                    if (align > vmin && align > EPSF) {
                        int j = TKK - 1;
                        while (j > 0 && align > lv[j - 1]) {
                            lv[j] = lv[j - 1]; lidx[j] = lidx[j - 1]; j--;
                        }
                        lv[j] = align; lidx[j] = n;
                        vmin = lv[TKK - 1];
                    }
                }
            }
        }
    }

    // block merge of per-thread top-10 lists; scatter winners into g_mask
    __shared__ float sv[128];
    __shared__ int si[128];
    int ptr = 0;
    for (int r = 0; r < TKK; r++) {
        float cv = (ptr < TKK) ? lv[ptr] : -2.0f;
        int ci = (ptr < TKK) ? lidx[ptr] : 0x7FFFFFFF;
        sv[threadIdx.x] = cv; si[threadIdx.x] = ci;
        __syncthreads();
        for (int s = 64; s > 0; s >>= 1) {
            if (threadIdx.x < s) {
                float v2 = sv[threadIdx.x + s]; int i2 = si[threadIdx.x + s];
                if (v2 > sv[threadIdx.x] ||
                    (v2 == sv[threadIdx.x] && i2 < si[threadIdx.x])) {
                    sv[threadIdx.x] = v2; si[threadIdx.x] = i2;
                }
            }
            __syncthreads();
        }
        float bestv = sv[0]; int besti = si[0];
        if (threadIdx.x == 0 && bestv > EPSF)
            atomicOr(&g_mask[b * NN + besti], 1u << gidx);
        if (ptr < TKK && lidx[ptr] == besti && lv[ptr] == bestv) ptr++;
        __syncthreads();
    }
}

// ---------------- k_select: mask-driven sparse assignment + CIoU + DFL ----------------
__global__ void k_select(const float* __restrict__ p0,
                         const float* __restrict__ p1,
                         const float* __restrict__ p2,
                         const float* __restrict__ gt,
                         const int* __restrict__ lab) {
    __shared__ float4 s_gt[GG];
    __shared__ int s_lab[GG];
    int b = blockIdx.y;
    if (threadIdx.x < GG) {
        s_gt[threadIdx.x] = *reinterpret_cast<const float4*>(gt + ((size_t)b * GG + threadIdx.x) * 4);
        s_lab[threadIdx.x] = lab[b * GG + threadIdx.x];
    }
    __syncthreads();

    int n = blockIdx.x * blockDim.x + threadIdx.x;
    float liou = 0.f, ldfl = 0.f;
    int fgflag = 0;

    if (n < NN) {
        unsigned mask = g_mask[b * NN + n];
        if (mask) {
            fgflag = 1;
            float4 pb = *reinterpret_cast<const float4*>(g_boxes + ((size_t)b * NN + n) * 4);
            int mg;
            if (mask & (mask - 1)) {          // count > 1: argmax iou over ALL GTs
                float bi = -1.f; int bgi = 0;
#pragma unroll
                for (int g = 0; g < GG; g++) {
                    float4 Gg = s_gt[g];
                    float agg = fmaxf(Gg.z - Gg.x, 0.f) * fmaxf(Gg.w - Gg.y, 0.f);
                    float iou = iou_gt_pred(Gg.x, Gg.y, Gg.z, Gg.w, agg, pb.x, pb.y, pb.z, pb.w);
                    if (iou > bi) { bi = iou; bgi = g; }
                }
                mg = bgi;
            } else {
                mg = __ffs(mask) - 1;
            }

            int lvl, HW, local; float cx, cy;
            locate(n, lvl, HW, local, cx, cy);
            float4 Gm = s_gt[mg];
            float tx1 = Gm.x, ty1 = Gm.y, tx2 = Gm.z, ty2 = Gm.w;
            float ag = fmaxf(tx2 - tx1, 0.f) * fmaxf(ty2 - ty1, 0.f);
            float iou_m = iou_gt_pred(tx1, ty1, tx2, ty2, ag, pb.x, pb.y, pb.z, pb.w);
            bool mgt = (tx1 + ty1 + tx2 + ty2) > 0.f;
            bool ing = (cx > tx1) && (cx < tx2) && (cy > ty1) && (cy < ty2);

            const float* p = (lvl == 0) ? p0 : ((lvl == 1) ? p1 : p2);
            const float* dbase = p + (size_t)b * 144 * HW + local;

            float a = 0.f;
            if (ing && mgt) {
                int label = s_lab[mg];
                float sc = dbase[(size_t)(64 + label) * HW];
                float prob = __fdividef(1.f, 1.f + __expf(-sc));
                float i2 = iou_m * iou_m;
                a = sqrtf(prob) * (i2 * i2 * i2);
                if (a > 0.f)
                    atomicAdd(&g_SA[b * GG + mg], (double)(sc * a));
            }
            atomicMax(&g_posA[b * GG + mg], __float_as_uint(a));
            atomicMax(&g_posI[b * GG + mg], __float_as_uint(iou_m));

            // CIoU loss
            float px1 = pb.x, py1 = pb.y, px2 = pb.z, py2 = pb.w;
            float w1 = px2 - px1, h1 = py2 - py1;
            float w2 = tx2 - tx1, h2 = ty2 - ty1;
            float iw = fmaxf(fminf(px2, tx2) - fmaxf(px1, tx1), 0.f);
            float ih = fmaxf(fminf(py2, ty2) - fmaxf(py1, ty1), 0.f);
            float inter = iw * ih;
            float uni = w1 * h1 + w2 * h2 - inter + 1e-7f;
            float iou = inter / uni;
            float cw = fmaxf(px2, tx2) - fminf(px1, tx1);
            float ch = fmaxf(py2, ty2) - fminf(py1, ty1);
            float c2 = cw * cw + ch * ch + 1e-7f;
            float dxs = px1 + px2 - tx1 - tx2;
            float dys = py1 + py2 - ty1 - ty2;
            float rho2 = (dxs * dxs + dys * dys) * 0.25f;
            float dv = atanf(w2 / (h2 + 1e-7f)) - atanf(w1 / (h1 + 1e-7f));
            const float c4pi2 = 4.0f / (3.14159265358979323846f * 3.14159265358979323846f);
            float v = c4pi2 * dv * dv;
            float alpha = v / (v - iou + 1.0f + 1e-7f);
            liou = 1.f - (iou - rho2 / c2 - alpha * v);

            // DFL loss
            float ds[4] = { fmaxf(cx - tx1, 0.f), fmaxf(cy - ty1, 0.f),
                            fmaxf(tx2 - cx, 0.f), fmaxf(ty2 - cy, 0.f) };
#pragma unroll
            for (int k = 0; k < 4; k++) {
                float tbv = fminf(ds[k], 14.999999f);
                int li = (int)tbv;
                float aa = tbv - (float)li;
                int ui = min(li + 1, 15);
                float vv[16]; float mx = -1e30f;
#pragma unroll
                for (int j = 0; j < 16; j++) {
                    vv[j] = dbase[(size_t)(k * 16 + j) * HW];
                    mx = fmaxf(mx, vv[j]);
                }
                float se = 0.f;
#pragma unroll
                for (int j = 0; j < 16; j++) se += __expf(vv[j] - mx);
                float lse = __logf(se) + mx;
                ldfl += -((1.f - aa) * (vv[li] - lse) + aa * (vv[ui] - lse));
            }
        }
    }

    // warp-aggregated fg count
    unsigned msk = __ballot_sync(0xffffffffu, fgflag);
    if ((threadIdx.x & 31) == 0 && msk) atomicAdd(&g_fgcnt, (int)__popc(msk));

    // block reduce only if some thread in the block had fg work
    if (__syncthreads_or(fgflag)) {
        __shared__ float r1[256], r2[256];
        r1[threadIdx.x] = liou; r2[threadIdx.x] = ldfl;
        __syncthreads();
        for (int s = 128; s > 0; s >>= 1) {
            if (threadIdx.x < s) {
                r1[threadIdx.x] += r1[threadIdx.x + s];
                r2[threadIdx.x] += r2[threadIdx.x + s];
            }
            __syncthreads();
        }
        if (threadIdx.x == 0) {
            if (r1[0] != 0.f) atomicAdd(&g_iou_sum, (double)r1[0]);
            if (r2[0] != 0.f) atomicAdd(&g_dfl_sum, (double)r2[0]);
        }
    }
}

// ---------------- k_final: cross term + outputs ----------------
__global__ void k_final(float* __restrict__ out) {
    __shared__ double sred[256];
    double c = 0.0;
    for (int i = threadIdx.x; i < BB * GG; i += 256) {
        float pA = __uint_as_float(g_posA[i]);
        float pI = __uint_as_float(g_posI[i]);
        c += g_SA[i] * (double)(pI / (pA + EPSF));
    }
    sred[threadIdx.x] = c;
    __syncthreads();
    for (int s = 128; s > 0; s >>= 1) {
        if (threadIdx.x < s) sred[threadIdx.x] += sred[threadIdx.x + s];
        __syncthreads();
    }
    if (threadIdx.x == 0) {
        double np = (double)g_fgcnt;
        if (np < 1.0) np = 1.0;
        out[0] = (float)(7.5 * g_iou_sum / np);
        out[1] = (float)(0.5 * (g_bce - sred[0]) / np);
        out[2] = (float)(1.5 * g_dfl_sum / np);
    }
}

// ---------------- launch ----------------
extern "C" void kernel_launch(void* const* d_in, const int* in_sizes, int n_in,
                              void* d_out, int out_size) {
    const float* p0 = (const float*)d_in[0];
    const float* p1 = (const float*)d_in[1];
    const float* p2 = (const float*)d_in[2];
    const float* gt = (const float*)d_in[3];
    const int* lab = (const int*)d_in[4];
    float* out = (float*)d_out;

    k_init<<<(BB * NN + 255) / 256, 256>>>();
    {
        dim3 gdec((NN / 4 + 127) / 128, BB);
        k_decode_bce<<<gdec, 128>>>(p0, p1, p2);
    }
    k_align_topk<<<BB * GG, 128>>>(p0, p1, p2, gt, lab);
    {
        dim3 gsel((NN + 255) / 256, BB);
        k_select<<<gsel, 256>>>(p0, p1, p2, gt, lab);
    }
    k_final<<<1, 256>>>(out);
}